// round 11
// baseline (speedup 1.0000x reference)
#include <cuda_runtime.h>
#include <cuda_bf16.h>

#define BB 8
#define NQ 200
#define NN 100
#define SS 4096
#define EE 2048
#define HH 8
#define CH 256

// ------------- scratch (device bss) -------------
__device__ float g_qp[(size_t)BB * NQ * EE];
__device__ float g_kp[(size_t)BB * SS * EE];
__device__ float g_vp[(size_t)BB * SS * EE];
__device__ float g_kinv[BB * SS];
__device__ float g_q1[(size_t)BB * NN * EE];
__device__ int   g_widx[BB * HH * SS];
__device__ float g_att[(size_t)BB * HH * NN * SS];
__device__ float g_cat[(size_t)BB * NQ * EE];

// ------------- f32x2 helpers -------------
__device__ __forceinline__ unsigned long long pack2(float lo, float hi) {
    unsigned long long r;
    asm("mov.b64 %0, {%1, %2};" : "=l"(r) : "f"(lo), "f"(hi));
    return r;
}
__device__ __forceinline__ void unpack2(unsigned long long p, float& lo, float& hi) {
    asm("mov.b64 {%0, %1}, %2;" : "=f"(lo), "=f"(hi) : "l"(p));
}
__device__ __forceinline__ unsigned long long ffma2(unsigned long long a,
                                                    unsigned long long b,
                                                    unsigned long long c) {
    unsigned long long d;
    asm("fma.rn.f32x2 %0, %1, %2, %3;" : "=l"(d) : "l"(a), "l"(b), "l"(c));
    return d;
}

// ------------- JAX threefry2x32 Gumbel (key=[0,42], partitionable) -------------
// partitionable scheme: counter = (hi=0, lo=i); 32-bit draw = out0 ^ out1.
__device__ __forceinline__ float gumbel_g(unsigned int ctr) {
    unsigned int x0 = 0u, x1 = ctr;
    const unsigned int k0 = 0u, k1 = 42u, k2 = 0x1BD11BDAu ^ 42u;
    x0 += k0; x1 += k1;
#define TFR(r) { x0 += x1; x1 = (x1 << (r)) | (x1 >> (32 - (r))); x1 ^= x0; }
    TFR(13) TFR(15) TFR(26) TFR(6)
    x0 += k1; x1 += k2 + 1u;
    TFR(17) TFR(29) TFR(16) TFR(24)
    x0 += k2; x1 += k0 + 2u;
    TFR(13) TFR(15) TFR(26) TFR(6)
    x0 += k0; x1 += k1 + 3u;
    TFR(17) TFR(29) TFR(16) TFR(24)
    x0 += k1; x1 += k2 + 4u;
    TFR(13) TFR(15) TFR(26) TFR(6)
    x0 += k2; x1 += k0 + 5u;
#undef TFR
    unsigned int bits = x0 ^ x1;   // <-- partitionable 32-bit draw: XOR of both words
    float f = __uint_as_float((bits >> 9) | 0x3f800000u) - 1.0f;
    const float minv = 1e-6f;
    const float maxv = (float)(1.0 - 1e-6);
    const float span = maxv - minv;                 // f32 sub, as in jnp
    float u = __fadd_rn(__fmul_rn(f, span), minv);  // unfused mul+add (XLA)
    u = fmaxf(minv, u);
    return -logf(-logf(u));
}

// ------------- generic f32x2 GEMM: C = A(MxK)@W(KxN) (+bias) -------------
// tiles 128x128x16, 256 threads, 8x8 accum per thread (f32x2 pairs).
// z-batched via (b = z>>3, h = z&7) offsets; all offsets 0 for flat GEMMs.
__global__ __launch_bounds__(256) void sgemm_f32x2(
    const float* __restrict__ A, int lda, size_t aZb, size_t aZh,
    const float* __restrict__ W, int ldw, size_t wZb, size_t wZh,
    float* __restrict__ C, int ldc, size_t cZb, size_t cZh,
    const float* __restrict__ bias, int M, int K)
{
    __shared__ __align__(16) float As[16][128];
    __shared__ __align__(16) float Ws[16][128];
    const int tid  = threadIdx.x;
    const int tm   = (tid >> 4) * 8;
    const int tn   = (tid & 15) * 8;
    const int row0 = blockIdx.y * 128;
    const int col0 = blockIdx.x * 128;
    const int zb = blockIdx.z >> 3, zh = blockIdx.z & 7;
    const float* Az = A + (size_t)zb * aZb + (size_t)zh * aZh;
    const float* Wz = W + (size_t)zb * wZb + (size_t)zh * wZh;
    float* Cz       = C + (size_t)zb * cZb + (size_t)zh * cZh;

    unsigned long long acc[8][4];
#pragma unroll
    for (int i = 0; i < 8; i++)
#pragma unroll
        for (int j = 0; j < 4; j++) acc[i][j] = 0ull;

    const int la_r = tid >> 2, la_c = (tid & 3) * 4;
    const int lw_r = tid >> 5, lw_c = (tid & 31) * 4;

    for (int k0 = 0; k0 < K; k0 += 16) {
#pragma unroll
        for (int i = 0; i < 2; i++) {
            int ar = la_r + i * 64;
            float4 av = make_float4(0.f, 0.f, 0.f, 0.f);
            if (row0 + ar < M)
                av = *(const float4*)(Az + (size_t)(row0 + ar) * lda + k0 + la_c);
            As[la_c + 0][ar] = av.x; As[la_c + 1][ar] = av.y;
            As[la_c + 2][ar] = av.z; As[la_c + 3][ar] = av.w;
        }
#pragma unroll
        for (int i = 0; i < 2; i++) {
            int wr = lw_r + i * 8;
            *(float4*)&Ws[wr][lw_c] =
                *(const float4*)(Wz + (size_t)(k0 + wr) * ldw + col0 + lw_c);
        }
        __syncthreads();
#pragma unroll
        for (int kk = 0; kk < 16; kk++) {
            float a[8], b[8];
            *(float4*)&a[0] = *(const float4*)&As[kk][tm];
            *(float4*)&a[4] = *(const float4*)&As[kk][tm + 4];
            *(float4*)&b[0] = *(const float4*)&Ws[kk][tn];
            *(float4*)&b[4] = *(const float4*)&Ws[kk][tn + 4];
            unsigned long long bp[4];
#pragma unroll
            for (int j = 0; j < 4; j++) bp[j] = pack2(b[2 * j], b[2 * j + 1]);
#pragma unroll
            for (int i = 0; i < 8; i++) {
                unsigned long long ap = pack2(a[i], a[i]);
#pragma unroll
                for (int j = 0; j < 4; j++) acc[i][j] = ffma2(ap, bp[j], acc[i][j]);
            }
        }
        __syncthreads();
    }

#pragma unroll
    for (int i = 0; i < 8; i++) {
        int r = row0 + tm + i;
        if (r < M) {
            float o[8];
#pragma unroll
            for (int j = 0; j < 4; j++) unpack2(acc[i][j], o[2 * j], o[2 * j + 1]);
            if (bias) {
#pragma unroll
                for (int j = 0; j < 8; j++) o[j] += bias[col0 + tn + j];
            }
            *(float4*)(Cz + (size_t)r * ldc + col0 + tn)     = make_float4(o[0], o[1], o[2], o[3]);
            *(float4*)(Cz + (size_t)r * ldc + col0 + tn + 4) = make_float4(o[4], o[5], o[6], o[7]);
        }
    }
}

// ------------- kp row inverse norms -------------
__global__ __launch_bounds__(256) void knorm_kernel(const float* __restrict__ kp,
                                                    float* __restrict__ kinv)
{
    __shared__ float red[8];
    const float* p = kp + (size_t)blockIdx.x * EE;
    float ss = 0.f;
#pragma unroll
    for (int it = 0; it < 2; it++) {
        float4 v = *(const float4*)(p + threadIdx.x * 4 + it * 1024);
        ss += v.x * v.x + v.y * v.y + v.z * v.z + v.w * v.w;
    }
#pragma unroll
    for (int o = 16; o; o >>= 1) ss += __shfl_xor_sync(0xffffffffu, ss, o);
    if ((threadIdx.x & 31) == 0) red[threadIdx.x >> 5] = ss;
    __syncthreads();
    if (threadIdx.x == 0) {
        float t = 0.f;
#pragma unroll
        for (int w = 0; w < 8; w++) t += red[w];
        kinv[blockIdx.x] = 1.0f / sqrtf(t);
    }
}

// ------------- q1 = normalize(qp rows [:,0:100,:]) -------------
__global__ __launch_bounds__(256) void q1norm_kernel(const float* __restrict__ qp,
                                                     float* __restrict__ q1)
{
    __shared__ float red[8];
    __shared__ float s_inv;
    int row = blockIdx.x;                 // 0..799
    int b = row / NN, qq = row % NN;
    const float* p = qp + (size_t)(b * NQ + qq) * EE;
    float ss = 0.f;
#pragma unroll
    for (int it = 0; it < 2; it++) {
        float4 v = *(const float4*)(p + threadIdx.x * 4 + it * 1024);
        ss += v.x * v.x + v.y * v.y + v.z * v.z + v.w * v.w;
    }
#pragma unroll
    for (int o = 16; o; o >>= 1) ss += __shfl_xor_sync(0xffffffffu, ss, o);
    if ((threadIdx.x & 31) == 0) red[threadIdx.x >> 5] = ss;
    __syncthreads();
    if (threadIdx.x == 0) {
        float t = 0.f;
#pragma unroll
        for (int w = 0; w < 8; w++) t += red[w];
        s_inv = 1.0f / sqrtf(t);
    }
    __syncthreads();
    float inv = s_inv;
    float* dst = q1 + (size_t)row * EE;
#pragma unroll
    for (int it = 0; it < 2; it++) {
        int i = threadIdx.x * 4 + it * 1024;
        float4 v = *(const float4*)(p + i);
        v.x *= inv; v.y *= inv; v.z *= inv; v.w *= inv;
        *(float4*)(dst + i) = v;
    }
}

// ------------- fused attn1-argmax + attn2-logits -------------
// grid (S/64, 1, B*H); 256 threads; tile 128q x 64s from shared kp tile.
__global__ __launch_bounds__(256) void attn_fused_kernel(
    const float* __restrict__ kp, const float* __restrict__ kinv,
    const float* __restrict__ q1, const float* __restrict__ qp,
    float* __restrict__ att, int* __restrict__ widx)
{
    __shared__ __align__(16) float As1[16][128];
    __shared__ __align__(16) float As2[16][128];
    __shared__ __align__(16) float Bs[16][64];
    __shared__ float rbest[64][16];
    __shared__ int   rq[64][16];

    const int tid = threadIdx.x;
    const int bh = blockIdx.z;
    const int b = bh >> 3, h = bh & 7;
    const int s0 = blockIdx.x * 64;
    const int tm = (tid >> 4) * 8;
    const int tn = (tid & 15) * 4;

    float acc1[8][4] = {}, acc2[8][4] = {};

    for (int c0 = 0; c0 < CH; c0 += 16) {
#pragma unroll
        for (int i = 0; i < 2; i++) {
            int ar = (tid >> 2) + i * 64;
            int ac = (tid & 3) * 4;
            float4 v1 = make_float4(0.f, 0.f, 0.f, 0.f), v2 = v1;
            if (ar < NN) {
                v1 = *(const float4*)(q1 + (size_t)(b * NN + ar) * EE + h * CH + c0 + ac);
                v2 = *(const float4*)(qp + (size_t)(b * NQ + NN + ar) * EE + h * CH + c0 + ac);
            }
            As1[ac + 0][ar] = v1.x; As1[ac + 1][ar] = v1.y; As1[ac + 2][ar] = v1.z; As1[ac + 3][ar] = v1.w;
            As2[ac + 0][ar] = v2.x; As2[ac + 1][ar] = v2.y; As2[ac + 2][ar] = v2.z; As2[ac + 3][ar] = v2.w;
        }
        {
            int sl = tid >> 2, cl = (tid & 3) * 4;
            float4 kv = *(const float4*)(kp + (size_t)(b * SS + s0 + sl) * EE + h * CH + c0 + cl);
            Bs[cl + 0][sl] = kv.x; Bs[cl + 1][sl] = kv.y; Bs[cl + 2][sl] = kv.z; Bs[cl + 3][sl] = kv.w;
        }
        __syncthreads();
#pragma unroll
        for (int kk = 0; kk < 16; kk++) {
            float a1[8], a2[8], bb[4];
            *(float4*)&a1[0] = *(const float4*)&As1[kk][tm];
            *(float4*)&a1[4] = *(const float4*)&As1[kk][tm + 4];
            *(float4*)&a2[0] = *(const float4*)&As2[kk][tm];
            *(float4*)&a2[4] = *(const float4*)&As2[kk][tm + 4];
            *(float4*)&bb[0] = *(const float4*)&Bs[kk][tn];
#pragma unroll
            for (int i = 0; i < 8; i++)
#pragma unroll
                for (int j = 0; j < 4; j++) {
                    acc1[i][j] = fmaf(a1[i], bb[j], acc1[i][j]);
                    acc2[i][j] = fmaf(a2[i], bb[j], acc2[i][j]);
                }
        }
        __syncthreads();
    }

    float kiv[4];
#pragma unroll
    for (int j = 0; j < 4; j++) kiv[j] = kinv[b * SS + s0 + tn + j];

    float best[4]; int bq[4];
#pragma unroll
    for (int j = 0; j < 4; j++) { best[j] = -3.0e38f; bq[j] = 0; }

#pragma unroll
    for (int i = 0; i < 8; i++) {
        int qv = tm + i;
        if (qv < NN) {
            float4 st;                           // attn2 logits /16
            st.x = acc2[i][0] * 0.0625f; st.y = acc2[i][1] * 0.0625f;
            st.z = acc2[i][2] * 0.0625f; st.w = acc2[i][3] * 0.0625f;
            *(float4*)(att + (size_t)(bh * NN + qv) * SS + s0 + tn) = st;
#pragma unroll
            for (int j = 0; j < 4; j++) {
                unsigned int ctr = ((unsigned int)(bh * NN + qv) << 12)
                                 | (unsigned int)(s0 + tn + j);
                float val = acc1[i][j] * kiv[j] + gumbel_g(ctr);
                if (val > best[j]) { best[j] = val; bq[j] = qv; }
            }
        }
    }
#pragma unroll
    for (int j = 0; j < 4; j++) {
        rbest[tn + j][tid >> 4] = best[j];
        rq[tn + j][tid >> 4]    = bq[j];
    }
    __syncthreads();
    if (tid < 64) {
        float bv = rbest[tid][0]; int bqq = rq[tid][0];
#pragma unroll
        for (int r = 1; r < 16; r++) {
            float vv = rbest[tid][r]; int qq = rq[tid][r];
            if (vv > bv || (vv == bv && qq < bqq)) { bv = vv; bqq = qq; }
        }
        widx[bh * SS + s0 + tid] = bqq;
    }
}

// ------------- softmax over 4096-wide rows of g_att (in place) -------------
__global__ __launch_bounds__(256) void softmax_kernel(float* __restrict__ att)
{
    __shared__ float red[8];
    __shared__ float s_b;
    float* p = att + (size_t)blockIdx.x * SS;
    float v[16];
#pragma unroll
    for (int c = 0; c < 4; c++) {
        float4 t = *(const float4*)(p + threadIdx.x * 4 + c * 1024);
        v[c * 4 + 0] = t.x; v[c * 4 + 1] = t.y; v[c * 4 + 2] = t.z; v[c * 4 + 3] = t.w;
    }
    float m = -3.0e38f;
#pragma unroll
    for (int i = 0; i < 16; i++) m = fmaxf(m, v[i]);
#pragma unroll
    for (int o = 16; o; o >>= 1) m = fmaxf(m, __shfl_xor_sync(0xffffffffu, m, o));
    if ((threadIdx.x & 31) == 0) red[threadIdx.x >> 5] = m;
    __syncthreads();
    if (threadIdx.x == 0) {
        float t = red[0];
#pragma unroll
        for (int w = 1; w < 8; w++) t = fmaxf(t, red[w]);
        s_b = t;
    }
    __syncthreads();
    float mx = s_b;
    float s = 0.f;
#pragma unroll
    for (int i = 0; i < 16; i++) { v[i] = expf(v[i] - mx); s += v[i]; }
#pragma unroll
    for (int o = 16; o; o >>= 1) s += __shfl_xor_sync(0xffffffffu, s, o);
    __syncthreads();
    if ((threadIdx.x & 31) == 0) red[threadIdx.x >> 5] = s;
    __syncthreads();
    if (threadIdx.x == 0) {
        float t = 0.f;
#pragma unroll
        for (int w = 0; w < 8; w++) t += red[w];
        s_b = t;
    }
    __syncthreads();
    float sum = s_b;
#pragma unroll
    for (int c = 0; c < 4; c++) {
        float4 t;
        t.x = v[c * 4 + 0] / sum; t.y = v[c * 4 + 1] / sum;
        t.z = v[c * 4 + 2] / sum; t.w = v[c * 4 + 3] / sum;
        *(float4*)(p + threadIdx.x * 4 + c * 1024) = t;
    }
}

// ------------- out1: ordered gather of vp rows by argmax winner -------------
__global__ __launch_bounds__(256) void out1_gather_kernel(
    const float* __restrict__ vp, const int* __restrict__ widx,
    float* __restrict__ cat)
{
    __shared__ int sw[SS];
    int qv = blockIdx.x;                 // 0..99
    int bh = blockIdx.y;                 // 0..63
    int b = bh >> 3, h = bh & 7;
    const int* wsrc = widx + bh * SS;
    for (int i = threadIdx.x; i < SS; i += 256) sw[i] = wsrc[i];
    __syncthreads();
    int c = threadIdx.x;
    const float* vbase = vp + (size_t)b * SS * EE + h * CH + c;
    float acc = 0.f;
    for (int s = 0; s < SS; s++)
        if (sw[s] == qv) acc += vbase[(size_t)s * EE];
    cat[((size_t)b * NQ + qv) * EE + h * CH + c] = acc;
}

// ------------- launcher -------------
extern "C" void kernel_launch(void* const* d_in, const int* in_sizes, int n_in,
                              void* d_out, int out_size) {
    const float* q  = (const float*)d_in[0];
    const float* k  = (const float*)d_in[1];
    const float* v  = (const float*)d_in[2];
    const float* wq = (const float*)d_in[3];
    const float* bq = (const float*)d_in[4];
    const float* wk = (const float*)d_in[5];
    const float* bk = (const float*)d_in[6];
    const float* wv = (const float*)d_in[7];
    const float* bv = (const float*)d_in[8];
    const float* wo = (const float*)d_in[9];
    const float* bo = (const float*)d_in[10];
    float* out = (float*)d_out;

    float *qp, *kp, *vp, *kinv, *q1, *att, *cat; int* widx;
    cudaGetSymbolAddress((void**)&qp,   g_qp);
    cudaGetSymbolAddress((void**)&kp,   g_kp);
    cudaGetSymbolAddress((void**)&vp,   g_vp);
    cudaGetSymbolAddress((void**)&kinv, g_kinv);
    cudaGetSymbolAddress((void**)&q1,   g_q1);
    cudaGetSymbolAddress((void**)&widx, g_widx);
    cudaGetSymbolAddress((void**)&att,  g_att);
    cudaGetSymbolAddress((void**)&cat,  g_cat);

    dim3 blk(256);
    // projections
    sgemm_f32x2<<<dim3(16, 13, 1),  blk>>>(q, EE, 0, 0, wq, EE, 0, 0, qp, EE, 0, 0, bq, BB * NQ, EE);
    sgemm_f32x2<<<dim3(16, 256, 1), blk>>>(k, EE, 0, 0, wk, EE, 0, 0, kp, EE, 0, 0, bk, BB * SS, EE);
    sgemm_f32x2<<<dim3(16, 256, 1), blk>>>(v, EE, 0, 0, wv, EE, 0, 0, vp, EE, 0, 0, bv, BB * SS, EE);
    // norms
    knorm_kernel<<<BB * SS, blk>>>(kp, kinv);
    q1norm_kernel<<<BB * NN, blk>>>(qp, q1);
    // fused attn logits + gumbel argmax
    attn_fused_kernel<<<dim3(SS / 64, 1, BB * HH), blk>>>(kp, kinv, q1, qp, att, widx);
    // attn2 softmax
    softmax_kernel<<<BB * HH * NN, blk>>>(att);
    // out1 gather  ->  cat rows [0,100)
    out1_gather_kernel<<<dim3(NN, BB * HH), blk>>>(vp, widx, cat);
    // out2 = P @ Vh  ->  cat rows [100,200)
    sgemm_f32x2<<<dim3(2, 1, BB * HH), blk>>>(
        att, SS, (size_t)HH * NN * SS, (size_t)NN * SS,
        vp,  EE, (size_t)SS * EE,      (size_t)CH,
        cat + (size_t)NN * EE, EE, (size_t)NQ * EE, (size_t)CH,
        nullptr, NN, SS);
    // final projection
    sgemm_f32x2<<<dim3(16, 13, 1), blk>>>(cat, EE, 0, 0, wo, EE, 0, 0, out, EE, 0, 0, bo, BB * NQ, EE);
    (void)in_sizes; (void)n_in; (void)out_size;
}

// round 13
// speedup vs baseline: 1.0458x; 1.0458x over previous
#include <cuda_runtime.h>
#include <cuda_bf16.h>
#include <cstdint>

#define BB 8
#define NQ 200
#define NN 100
#define SS 4096
#define EE 2048
#define HH 8
#define CH 256
#define KC 32
#define NC (EE / KC)          // 64 k-chunks
#define TILEB 10240           // 128 rows x 80B (32 bf16 + 8 pad)

// ------------- scratch (device bss) -------------
__device__ float g_qp[(size_t)BB * NQ * EE];
__device__ float g_kp[(size_t)BB * SS * EE];
__device__ float g_vp[(size_t)BB * SS * EE];
__device__ float g_kinv[BB * SS];
__device__ float g_q1[(size_t)BB * NN * EE];
__device__ int   g_widx[BB * HH * SS];
__device__ float g_att[(size_t)BB * HH * NN * SS];
__device__ float g_cat[(size_t)BB * NQ * EE];
// bf16 splits of activations (k, v) and transposed weights (wk^T, wv^T)
__device__ __nv_bfloat16 g_ka1[(size_t)BB * SS * EE];
__device__ __nv_bfloat16 g_ka2[(size_t)BB * SS * EE];
__device__ __nv_bfloat16 g_ka3[(size_t)BB * SS * EE];
__device__ __nv_bfloat16 g_va1[(size_t)BB * SS * EE];
__device__ __nv_bfloat16 g_va2[(size_t)BB * SS * EE];
__device__ __nv_bfloat16 g_va3[(size_t)BB * SS * EE];
__device__ __nv_bfloat16 g_wk1[(size_t)EE * EE];
__device__ __nv_bfloat16 g_wk2[(size_t)EE * EE];
__device__ __nv_bfloat16 g_wk3[(size_t)EE * EE];
__device__ __nv_bfloat16 g_wv1[(size_t)EE * EE];
__device__ __nv_bfloat16 g_wv2[(size_t)EE * EE];
__device__ __nv_bfloat16 g_wv3[(size_t)EE * EE];

__device__ const int d_pa[6] = {0, 0, 1, 1, 0, 2};
__device__ const int d_pb[6] = {0, 1, 0, 1, 2, 0};

// ------------- helpers -------------
__device__ __forceinline__ unsigned long long pack2(float lo, float hi) {
    unsigned long long r;
    asm("mov.b64 %0, {%1, %2};" : "=l"(r) : "f"(lo), "f"(hi));
    return r;
}
__device__ __forceinline__ void unpack2(unsigned long long p, float& lo, float& hi) {
    asm("mov.b64 {%0, %1}, %2;" : "=f"(lo), "=f"(hi) : "l"(p));
}
__device__ __forceinline__ unsigned long long ffma2(unsigned long long a,
                                                    unsigned long long b,
                                                    unsigned long long c) {
    unsigned long long d;
    asm("fma.rn.f32x2 %0, %1, %2, %3;" : "=l"(d) : "l"(a), "l"(b), "l"(c));
    return d;
}
__device__ __forceinline__ uint32_t s2u(const void* p) {
    uint32_t a;
    asm("{ .reg .u64 t; cvta.to.shared.u64 t, %1; cvt.u32.u64 %0, t; }" : "=r"(a) : "l"(p));
    return a;
}
__device__ __forceinline__ void cp16(uint32_t dst, const void* src) {
    asm volatile("cp.async.cg.shared.global [%0], [%1], 16;" :: "r"(dst), "l"(src));
}
__device__ __forceinline__ uint32_t lds32(uint32_t addr) {
    uint32_t v;
    asm volatile("ld.shared.b32 %0, [%1];" : "=r"(v) : "r"(addr));
    return v;
}
__device__ __forceinline__ void mma_bf16(float* d, uint32_t a0, uint32_t a1,
                                         uint32_t a2, uint32_t a3,
                                         uint32_t b0, uint32_t b1) {
    asm volatile(
        "mma.sync.aligned.m16n8k16.row.col.f32.bf16.bf16.f32 "
        "{%0,%1,%2,%3}, {%4,%5,%6,%7}, {%8,%9}, {%0,%1,%2,%3};"
        : "+f"(d[0]), "+f"(d[1]), "+f"(d[2]), "+f"(d[3])
        : "r"(a0), "r"(a1), "r"(a2), "r"(a3), "r"(b0), "r"(b1));
}

// ------------- JAX threefry2x32 Gumbel (key=[0,42], partitionable) -------------
__device__ __forceinline__ float gumbel_g(unsigned int ctr) {
    unsigned int x0 = 0u, x1 = ctr;
    const unsigned int k0 = 0u, k1 = 42u, k2 = 0x1BD11BDAu ^ 42u;
    x0 += k0; x1 += k1;
#define TFR(r) { x0 += x1; x1 = (x1 << (r)) | (x1 >> (32 - (r))); x1 ^= x0; }
    TFR(13) TFR(15) TFR(26) TFR(6)
    x0 += k1; x1 += k2 + 1u;
    TFR(17) TFR(29) TFR(16) TFR(24)
    x0 += k2; x1 += k0 + 2u;
    TFR(13) TFR(15) TFR(26) TFR(6)
    x0 += k0; x1 += k1 + 3u;
    TFR(17) TFR(29) TFR(16) TFR(24)
    x0 += k1; x1 += k2 + 4u;
    TFR(13) TFR(15) TFR(26) TFR(6)
    x0 += k2; x1 += k0 + 5u;
#undef TFR
    unsigned int bits = x0 ^ x1;   // partitionable 32-bit draw
    float f = __uint_as_float((bits >> 9) | 0x3f800000u) - 1.0f;
    const float minv = 1e-6f;
    const float maxv = (float)(1.0 - 1e-6);
    const float span = maxv - minv;
    float u = __fadd_rn(__fmul_rn(f, span), minv);
    u = fmaxf(minv, u);
    return -logf(-logf(u));
}

// ------------- generic f32x2 GEMM (qp / out2 / final; exact fp32) -------------
__global__ __launch_bounds__(256) void sgemm_f32x2(
    const float* __restrict__ A, int lda, size_t aZb, size_t aZh,
    const float* __restrict__ W, int ldw, size_t wZb, size_t wZh,
    float* __restrict__ C, int ldc, size_t cZb, size_t cZh,
    const float* __restrict__ bias, int M, int K)
{
    __shared__ __align__(16) float As[16][128];
    __shared__ __align__(16) float Ws[16][128];
    const int tid  = threadIdx.x;
    const int tm   = (tid >> 4) * 8;
    const int tn   = (tid & 15) * 8;
    const int row0 = blockIdx.y * 128;
    const int col0 = blockIdx.x * 128;
    const int zb = blockIdx.z >> 3, zh = blockIdx.z & 7;
    const float* Az = A + (size_t)zb * aZb + (size_t)zh * aZh;
    const float* Wz = W + (size_t)zb * wZb + (size_t)zh * wZh;
    float* Cz       = C + (size_t)zb * cZb + (size_t)zh * cZh;

    unsigned long long acc[8][4];
#pragma unroll
    for (int i = 0; i < 8; i++)
#pragma unroll
        for (int j = 0; j < 4; j++) acc[i][j] = 0ull;

    const int la_r = tid >> 2, la_c = (tid & 3) * 4;
    const int lw_r = tid >> 5, lw_c = (tid & 31) * 4;

    for (int k0 = 0; k0 < K; k0 += 16) {
#pragma unroll
        for (int i = 0; i < 2; i++) {
            int ar = la_r + i * 64;
            float4 av = make_float4(0.f, 0.f, 0.f, 0.f);
            if (row0 + ar < M)
                av = *(const float4*)(Az + (size_t)(row0 + ar) * lda + k0 + la_c);
            As[la_c + 0][ar] = av.x; As[la_c + 1][ar] = av.y;
            As[la_c + 2][ar] = av.z; As[la_c + 3][ar] = av.w;
        }
#pragma unroll
        for (int i = 0; i < 2; i++) {
            int wr = lw_r + i * 8;
            *(float4*)&Ws[wr][lw_c] =
                *(const float4*)(Wz + (size_t)(k0 + wr) * ldw + col0 + lw_c);
        }
        __syncthreads();
#pragma unroll
        for (int kk = 0; kk < 16; kk++) {
            float a[8], b[8];
            *(float4*)&a[0] = *(const float4*)&As[kk][tm];
            *(float4*)&a[4] = *(const float4*)&As[kk][tm + 4];
            *(float4*)&b[0] = *(const float4*)&Ws[kk][tn];
            *(float4*)&b[4] = *(const float4*)&Ws[kk][tn + 4];
            unsigned long long bp[4];
#pragma unroll
            for (int j = 0; j < 4; j++) bp[j] = pack2(b[2 * j], b[2 * j + 1]);
#pragma unroll
            for (int i = 0; i < 8; i++) {
                unsigned long long ap = pack2(a[i], a[i]);
#pragma unroll
                for (int j = 0; j < 4; j++) acc[i][j] = ffma2(ap, bp[j], acc[i][j]);
            }
        }
        __syncthreads();
    }

#pragma unroll
    for (int i = 0; i < 8; i++) {
        int r = row0 + tm + i;
        if (r < M) {
            float o[8];
#pragma unroll
            for (int j = 0; j < 4; j++) unpack2(acc[i][j], o[2 * j], o[2 * j + 1]);
            if (bias) {
#pragma unroll
                for (int j = 0; j < 8; j++) o[j] += bias[col0 + tn + j];
            }
            *(float4*)(Cz + (size_t)r * ldc + col0 + tn)     = make_float4(o[0], o[1], o[2], o[3]);
            *(float4*)(Cz + (size_t)r * ldc + col0 + tn + 4) = make_float4(o[4], o[5], o[6], o[7]);
        }
    }
}

// ------------- 3-way bf16 split of an fp32 tensor -------------
__global__ __launch_bounds__(256) void split3_kernel(
    const float* __restrict__ x, __nv_bfloat16* __restrict__ h1,
    __nv_bfloat16* __restrict__ h2, __nv_bfloat16* __restrict__ h3, size_t n)
{
    size_t i = (size_t)blockIdx.x * blockDim.x + threadIdx.x;
    size_t stride = (size_t)gridDim.x * blockDim.x;
    for (; i < n; i += stride) {
        float v = x[i];
        __nv_bfloat16 a = __float2bfloat16(v);
        float r1 = v - __bfloat162float(a);
        __nv_bfloat16 b = __float2bfloat16(r1);
        float r2 = r1 - __bfloat162float(b);
        h1[i] = a; h2[i] = b; h3[i] = __float2bfloat16(r2);
    }
}

// ------------- transpose (EExEE) + 3-way bf16 split: Wt[n][k] = W[k][n] -------------
__global__ __launch_bounds__(256) void tsplit_kernel(
    const float* __restrict__ w, __nv_bfloat16* __restrict__ t1,
    __nv_bfloat16* __restrict__ t2, __nv_bfloat16* __restrict__ t3)
{
    __shared__ float tile[32][33];
    int n0 = blockIdx.x * 32, k0 = blockIdx.y * 32;
    int tx = threadIdx.x & 31, ty = threadIdx.x >> 5;   // 32 x 8
#pragma unroll
    for (int i = 0; i < 4; i++)
        tile[ty + i * 8][tx] = w[(size_t)(k0 + ty + i * 8) * EE + n0 + tx];
    __syncthreads();
#pragma unroll
    for (int i = 0; i < 4; i++) {
        float v = tile[tx][ty + i * 8];
        __nv_bfloat16 a = __float2bfloat16(v);
        float r1 = v - __bfloat162float(a);
        __nv_bfloat16 b = __float2bfloat16(r1);
        float r2 = r1 - __bfloat162float(b);
        size_t o = (size_t)(n0 + ty + i * 8) * EE + k0 + tx;
        t1[o] = a; t2[o] = b; t3[o] = __float2bfloat16(r2);
    }
}

// ------------- bf16-split GEMM via mma.sync: C[M,2048] = A@Wt^T + bias -------------
// A splits [M,K] bf16 K-major; B splits Wt[N=2048,K] bf16 K-major.
// Block 128x128, 8 warps (each 64x32 via 4x4 m16n8k16 frags), 2-stage cp.async.
__global__ __launch_bounds__(256, 1) void mm_mma(
    const __nv_bfloat16* __restrict__ A1, const __nv_bfloat16* __restrict__ A2,
    const __nv_bfloat16* __restrict__ A3,
    const __nv_bfloat16* __restrict__ B1, const __nv_bfloat16* __restrict__ B2,
    const __nv_bfloat16* __restrict__ B3,
    float* __restrict__ C, const float* __restrict__ bias,
    int nsplit, int npairs)
{
    extern __shared__ __align__(16) char smem[];
    const int tid = threadIdx.x;
    const int wid = tid >> 5, lane = tid & 31;
    const int g = lane >> 2, tig = lane & 3;
    const int wm = (wid >> 2) * 64;      // warp m offset (0/64)
    const int wn = (wid & 3) * 32;       // warp n offset (0/32/64/96)
    const int n0 = blockIdx.x * 128;
    const int m0 = blockIdx.y * 128;
    const uint32_t sbase = s2u(smem);
    const int stageBytes = nsplit * 2 * TILEB;

    float d[4][4][4];
#pragma unroll
    for (int mt = 0; mt < 4; mt++)
#pragma unroll
        for (int nt = 0; nt < 4; nt++)
#pragma unroll
            for (int r = 0; r < 4; r++) d[mt][nt][r] = 0.f;

    const __nv_bfloat16* AP[3] = {A1, A2, A3};
    const __nv_bfloat16* BP[3] = {B1, B2, B3};

    // ---- stage loader: 2 x 16B per thread per tile ----
    auto load_stage = [&](int buf, int c) {
        uint32_t sb = sbase + (uint32_t)buf * stageBytes;
        const int idx0 = tid * 2;
        for (int sp = 0; sp < nsplit; sp++) {
            const char* ga = (const char*)AP[sp] + ((size_t)m0 * EE + (size_t)c * KC) * 2;
            const char* gb = (const char*)BP[sp] + ((size_t)n0 * EE + (size_t)c * KC) * 2;
            uint32_t ta = sb + sp * TILEB;
            uint32_t tb = sb + (nsplit + sp) * TILEB;
#pragma unroll
            for (int t = 0; t < 2; t++) {
                int idx = idx0 + t;
                int row = idx >> 2, ch = idx & 3;
                cp16(ta + row * 80 + ch * 16, ga + (size_t)row * (EE * 2) + ch * 16);
                cp16(tb + row * 80 + ch * 16, gb + (size_t)row * (EE * 2) + ch * 16);
            }
        }
        asm volatile("cp.async.commit_group;" ::: "memory");
    };

    load_stage(0, 0);

    for (int c = 0; c < NC; c++) {
        if (c + 1 < NC) {
            load_stage((c + 1) & 1, c + 1);
            asm volatile("cp.async.wait_group 1;" ::: "memory");
        } else {
            asm volatile("cp.async.wait_group 0;" ::: "memory");
        }
        __syncthreads();

        uint32_t sb = sbase + (uint32_t)(c & 1) * stageBytes;
        for (int p = 0; p < npairs; p++) {
            uint32_t aBase = sb + d_pa[p] * TILEB;
            uint32_t bBase = sb + (nsplit + d_pb[p]) * TILEB;
#pragma unroll
            for (int ks = 0; ks < 2; ks++) {
                const int kk = ks * 16;
                uint32_t bf[4][2];
#pragma unroll
                for (int nt = 0; nt < 4; nt++) {
                    uint32_t ba = bBase + (wn + nt * 8 + g) * 80 + (kk + tig * 2) * 2;
                    bf[nt][0] = lds32(ba);
                    bf[nt][1] = lds32(ba + 16);
                }
#pragma unroll
                for (int mt = 0; mt < 4; mt++) {
                    uint32_t aa = aBase + (wm + mt * 16 + g) * 80 + (kk + tig * 2) * 2;
                    uint32_t a0 = lds32(aa);
                    uint32_t a1 = lds32(aa + 8 * 80);
                    uint32_t a2 = lds32(aa + 16);
                    uint32_t a3 = lds32(aa + 8 * 80 + 16);
#pragma unroll
                    for (int nt = 0; nt < 4; nt++)
                        mma_bf16(d[mt][nt], a0, a1, a2, a3, bf[nt][0], bf[nt][1]);
                }
            }
        }
        __syncthreads();
    }

    // ---- epilogue: add bias, store fp32 ----
#pragma unroll
    for (int mt = 0; mt < 4; mt++) {
        int r0 = m0 + wm + mt * 16 + g;
#pragma unroll
        for (int nt = 0; nt < 4; nt++) {
            int col = n0 + wn + nt * 8 + tig * 2;
            float b0 = bias[col], b1 = bias[col + 1];
            float2 v0 = make_float2(d[mt][nt][0] + b0, d[mt][nt][1] + b1);
            float2 v1 = make_float2(d[mt][nt][2] + b0, d[mt][nt][3] + b1);
            *(float2*)(C + (size_t)r0 * EE + col)       = v0;
            *(float2*)(C + (size_t)(r0 + 8) * EE + col) = v1;
        }
    }
}

// ------------- kp row inverse norms -------------
__global__ __launch_bounds__(256) void knorm_kernel(const float* __restrict__ kp,
                                                    float* __restrict__ kinv)
{
    __shared__ float red[8];
    const float* p = kp + (size_t)blockIdx.x * EE;
    float ss = 0.f;
#pragma unroll
    for (int it = 0; it < 2; it++) {
        float4 v = *(const float4*)(p + threadIdx.x * 4 + it * 1024);
        ss += v.x * v.x + v.y * v.y + v.z * v.z + v.w * v.w;
    }
#pragma unroll
    for (int o = 16; o; o >>= 1) ss += __shfl_xor_sync(0xffffffffu, ss, o);
    if ((threadIdx.x & 31) == 0) red[threadIdx.x >> 5] = ss;
    __syncthreads();
    if (threadIdx.x == 0) {
        float t = 0.f;
#pragma unroll
        for (int w = 0; w < 8; w++) t += red[w];
        kinv[blockIdx.x] = 1.0f / sqrtf(t);
    }
}

// ------------- q1 = normalize(qp rows [:,0:100,:]) -------------
__global__ __launch_bounds__(256) void q1norm_kernel(const float* __restrict__ qp,
                                                     float* __restrict__ q1)
{
    __shared__ float red[8];
    __shared__ float s_inv;
    int row = blockIdx.x;
    int b = row / NN, qq = row % NN;
    const float* p = qp + (size_t)(b * NQ + qq) * EE;
    float ss = 0.f;
#pragma unroll
    for (int it = 0; it < 2; it++) {
        float4 v = *(const float4*)(p + threadIdx.x * 4 + it * 1024);
        ss += v.x * v.x + v.y * v.y + v.z * v.z + v.w * v.w;
    }
#pragma unroll
    for (int o = 16; o; o >>= 1) ss += __shfl_xor_sync(0xffffffffu, ss, o);
    if ((threadIdx.x & 31) == 0) red[threadIdx.x >> 5] = ss;
    __syncthreads();
    if (threadIdx.x == 0) {
        float t = 0.f;
#pragma unroll
        for (int w = 0; w < 8; w++) t += red[w];
        s_inv = 1.0f / sqrtf(t);
    }
    __syncthreads();
    float inv = s_inv;
    float* dst = q1 + (size_t)row * EE;
#pragma unroll
    for (int it = 0; it < 2; it++) {
        int i = threadIdx.x * 4 + it * 1024;
        float4 v = *(const float4*)(p + i);
        v.x *= inv; v.y *= inv; v.z *= inv; v.w *= inv;
        *(float4*)(dst + i) = v;
    }
}

// ------------- fused attn1-argmax + attn2-logits (exact fp32) -------------
__global__ __launch_bounds__(256) void attn_fused_kernel(
    const float* __restrict__ kp, const float* __restrict__ kinv,
    const float* __restrict__ q1, const float* __restrict__ qp,
    float* __restrict__ att, int* __restrict__ widx)
{
    __shared__ __align__(16) float As1[16][128];
    __shared__ __align__(16) float As2[16][128];
    __shared__ __align__(16) float Bs[16][64];
    __shared__ float rbest[64][16];
    __shared__ int   rq[64][16];

    const int tid = threadIdx.x;
    const int bh = blockIdx.z;
    const int b = bh >> 3, h = bh & 7;
    const int s0 = blockIdx.x * 64;
    const int tm = (tid >> 4) * 8;
    const int tn = (tid & 15) * 4;

    float acc1[8][4] = {}, acc2[8][4] = {};

    for (int c0 = 0; c0 < CH; c0 += 16) {
#pragma unroll
        for (int i = 0; i < 2; i++) {
            int ar = (tid >> 2) + i * 64;
            int ac = (tid & 3) * 4;
            float4 v1 = make_float4(0.f, 0.f, 0.f, 0.f), v2 = v1;
            if (ar < NN) {
                v1 = *(const float4*)(q1 + (size_t)(b * NN + ar) * EE + h * CH + c0 + ac);
                v2 = *(const float4*)(qp + (size_t)(b * NQ + NN + ar) * EE + h * CH + c0 + ac);
            }
            As1[ac + 0][ar] = v1.x; As1[ac + 1][ar] = v1.y; As1[ac + 2][ar] = v1.z; As1[ac + 3][ar] = v1.w;
            As2[ac + 0][ar] = v2.x; As2[ac + 1][ar] = v2.y; As2[ac + 2][ar] = v2.z; As2[ac + 3][ar] = v2.w;
        }
        {
            int sl = tid >> 2, cl = (tid & 3) * 4;
            float4 kv = *(const float4*)(kp + (size_t)(b * SS + s0 + sl) * EE + h * CH + c0 + cl);
            Bs[cl + 0][sl] = kv.x; Bs[cl + 1][sl] = kv.y; Bs[cl + 2][sl] = kv.z; Bs[cl + 3][sl] = kv.w;
        }
        __syncthreads();
#pragma unroll
        for (int kk = 0; kk < 16; kk++) {
            float a1[8], a2[8], bb[4];
            *(float4*)&a1[0] = *(const float4*)&As1[kk][tm];
            *(float4*)&a1[4] = *(const float4*)&As1[kk][tm + 4];
            *(float4*)&a2[0] = *(const float4*)&As2[kk][tm];
            *(float4*)&a2[4] = *(const float4*)&As2[kk][tm + 4];
            *(float4*)&bb[0] = *(const float4*)&Bs[kk][tn];
#pragma unroll
            for (int i = 0; i < 8; i++)
#pragma unroll
                for (int j = 0; j < 4; j++) {
                    acc1[i][j] = fmaf(a1[i], bb[j], acc1[i][j]);
                    acc2[i][j] = fmaf(a2[i], bb[j], acc2[i][j]);
                }
        }
        __syncthreads();
    }

    float kiv[4];
#pragma unroll
    for (int j = 0; j < 4; j++) kiv[j] = kinv[b * SS + s0 + tn + j];

    float best[4]; int bq[4];
#pragma unroll
    for (int j = 0; j < 4; j++) { best[j] = -3.0e38f; bq[j] = 0; }

#pragma unroll
    for (int i = 0; i < 8; i++) {
        int qv = tm + i;
        if (qv < NN) {
            float4 st;
            st.x = acc2[i][0] * 0.0625f; st.y = acc2[i][1] * 0.0625f;
            st.z = acc2[i][2] * 0.0625f; st.w = acc2[i][3] * 0.0625f;
            *(float4*)(att + (size_t)(bh * NN + qv) * SS + s0 + tn) = st;
#pragma unroll
            for (int j = 0; j < 4; j++) {
                unsigned int ctr = ((unsigned int)(bh * NN + qv) << 12)
                                 | (unsigned int)(s0 + tn + j);
                float val = acc1[i][j] * kiv[j] + gumbel_g(ctr);
                if (val > best[j]) { best[j] = val; bq[j] = qv; }
            }
        }
    }
#pragma unroll
    for (int j = 0; j < 4; j++) {
        rbest[tn + j][tid >> 4] = best[j];
        rq[tn + j][tid >> 4]    = bq[j];
    }
    __syncthreads();
    if (tid < 64) {
        float bv = rbest[tid][0]; int bqq = rq[tid][0];
#pragma unroll
        for (int r = 1; r < 16; r++) {
            float vv = rbest[tid][r]; int qq = rq[tid][r];
            if (vv > bv || (vv == bv && qq < bqq)) { bv = vv; bqq = qq; }
        }
        widx[bh * SS + s0 + tid] = bqq;
    }
}

// ------------- softmax over 4096-wide rows of g_att (in place) -------------
__global__ __launch_bounds__(256) void softmax_kernel(float* __restrict__ att)
{
    __shared__ float red[8];
    __shared__ float s_b;
    float* p = att + (size_t)blockIdx.x * SS;
    float v[16];
#pragma unroll
    for (int c = 0; c < 4; c++) {
        float4 t = *(const float4*)(p + threadIdx.x * 4 + c * 1024);
        v[c * 4 + 0] = t.x; v[c * 4 + 1] = t.y; v[c * 4 + 2] = t.z; v[c * 4 + 3] = t.w;
    }
    float m = -3.0e38f;
#pragma unroll
    for (int i = 0; i < 16; i++) m = fmaxf(m, v[i]);
#pragma unroll
    for (int o = 16; o; o >>= 1) m = fmaxf(m, __shfl_xor_sync(0xffffffffu, m, o));
    if ((threadIdx.x & 31) == 0) red[threadIdx.x >> 5] = m;
    __syncthreads();
    if (threadIdx.x == 0) {
        float t = red[0];
#pragma unroll
        for (int w = 1; w < 8; w++) t = fmaxf(t, red[w]);
        s_b = t;
    }
    __syncthreads();
    float mx = s_b;
    float s = 0.f;
#pragma unroll
    for (int i = 0; i < 16; i++) { v[i] = expf(v[i] - mx); s += v[i]; }
#pragma unroll
    for (int o = 16; o; o >>= 1) s += __shfl_xor_sync(0xffffffffu, s, o);
    __syncthreads();
    if ((threadIdx.x & 31) == 0) red[threadIdx.x >> 5] = s;
    __syncthreads();
    if (threadIdx.x == 0) {
        float t = 0.f;
#pragma unroll
        for (int w = 0; w < 8; w++) t += red[w];
        s_b = t;
    }
    __syncthreads();
    float sum = s_b;
#pragma unroll
    for (int c = 0; c < 4; c++) {
        float4 t;
        t.x = v[c * 4 + 0] / sum; t.y = v[c * 4 + 1] / sum;
        t.z = v[c * 4 + 2] / sum; t.w = v[c * 4 + 3] / sum;
        *(float4*)(p + threadIdx.x * 4 + c * 1024) = t;
    }
}

// ------------- out1: ordered gather of vp rows by argmax winner -------------
__global__ __launch_bounds__(256) void out1_gather_kernel(
    const float* __restrict__ vp, const int* __restrict__ widx,
    float* __restrict__ cat)
{
    __shared__ int sw[SS];
    int qv = blockIdx.x;
    int bh = blockIdx.y;
    int b = bh >> 3, h = bh & 7;
    const int* wsrc = widx + bh * SS;
    for (int i = threadIdx.x; i < SS; i += 256) sw[i] = wsrc[i];
    __syncthreads();
    int c = threadIdx.x;
    const float* vbase = vp + (size_t)b * SS * EE + h * CH + c;
    float acc = 0.f;
    for (int s = 0; s < SS; s++)
        if (sw[s] == qv) acc += vbase[(size_t)s * EE];
    cat[((size_t)b * NQ + qv) * EE + h * CH + c] = acc;
}

// ------------- launcher -------------
extern "C" void kernel_launch(void* const* d_in, const int* in_sizes, int n_in,
                              void* d_out, int out_size) {
    const float* q  = (const float*)d_in[0];
    const float* k  = (const float*)d_in[1];
    const float* v  = (const float*)d_in[2];
    const float* wq = (const float*)d_in[3];
    const float* bq = (const float*)d_in[4];
    const float* wk = (const float*)d_in[5];
    const float* bk = (const float*)d_in[6];
    const float* wv = (const float*)d_in[7];
    const float* bv = (const float*)d_in[8];
    const float* wo = (const float*)d_in[9];
    const float* bo = (const float*)d_in[10];
    float* out = (float*)d_out;

    float *qp, *kp, *vp, *kinv, *q1, *att, *cat; int* widx;
    __nv_bfloat16 *ka1, *ka2, *ka3, *va1, *va2, *va3;
    __nv_bfloat16 *wk1, *wk2, *wk3, *wv1, *wv2, *wv3;
    cudaGetSymbolAddress((void**)&qp,   g_qp);
    cudaGetSymbolAddress((void**)&kp,   g_kp);
    cudaGetSymbolAddress((void**)&vp,   g_vp);
    cudaGetSymbolAddress((void**)&kinv, g_kinv);
    cudaGetSymbolAddress((void**)&q1,   g_q1);
    cudaGetSymbolAddress((void**)&widx, g_widx);
    cudaGetSymbolAddress((void**)&att,  g_att);
    cudaGetSymbolAddress((void**)&cat,  g_cat);
    cudaGetSymbolAddress((void**)&ka1,  g_ka1);
    cudaGetSymbolAddress((void**)&ka2,  g_ka2);
    cudaGetSymbolAddress((void**)&ka3,  g_ka3);
    cudaGetSymbolAddress((void**)&va1,  g_va1);
    cudaGetSymbolAddress((void**)&va2,  g_va2);
    cudaGetSymbolAddress((void**)&va3,  g_va3);
    cudaGetSymbolAddress((void**)&wk1,  g_wk1);
    cudaGetSymbolAddress((void**)&wk2,  g_wk2);
    cudaGetSymbolAddress((void**)&wk3,  g_wk3);
    cudaGetSymbolAddress((void**)&wv1,  g_wv1);
    cudaGetSymbolAddress((void**)&wv2,  g_wv2);
    cudaGetSymbolAddress((void**)&wv3,  g_wv3);

    const int smem_kp = 2 * 3 * 2 * TILEB;   // 122880 (nsplit=3)
    const int smem_vp = 2 * 2 * 2 * TILEB;   // 81920  (nsplit=2)
    cudaFuncSetAttribute(mm_mma, cudaFuncAttributeMaxDynamicSharedMemorySize, smem_kp);

    dim3 blk(256);
    const size_t nkv = (size_t)BB * SS * EE;
    // bf16 splits of k, v and transposed+split wk, wv
    split3_kernel<<<8192, blk>>>(k, ka1, ka2, ka3, nkv);
    split3_kernel<<<8192, blk>>>(v, va1, va2, va3, nkv);
    tsplit_kernel<<<dim3(64, 64), blk>>>(wk, wk1, wk2, wk3);
    tsplit_kernel<<<dim3(64, 64), blk>>>(wv, wv1, wv2, wv3);
    // qp: exact fp32 (feeds q1/attn1 path)
    sgemm_f32x2<<<dim3(16, 13, 1), blk>>>(q, EE, 0, 0, wq, EE, 0, 0, qp, EE, 0, 0, bq, BB * NQ, EE);
    // kp: bf16x6 (fp32-equivalent, argmax-safe); vp: bf16x4 (error ~7.6e-6)
    mm_mma<<<dim3(16, 256), blk, smem_kp>>>(ka1, ka2, ka3, wk1, wk2, wk3, kp, bk, 3, 6);
    mm_mma<<<dim3(16, 256), blk, smem_vp>>>(va1, va2, va3, wv1, wv2, wv3, vp, bv, 2, 4);
    // norms
    knorm_kernel<<<BB * SS, blk>>>(kp, kinv);
    q1norm_kernel<<<BB * NN, blk>>>(qp, q1);
    // fused attn logits + gumbel argmax
    attn_fused_kernel<<<dim3(SS / 64, 1, BB * HH), blk>>>(kp, kinv, q1, qp, att, widx);
    // attn2 softmax
    softmax_kernel<<<BB * HH * NN, blk>>>(att);
    // out1 gather
    out1_gather_kernel<<<dim3(NN, BB * HH), blk>>>(vp, widx, cat);
    // out2 = P @ Vh
    sgemm_f32x2<<<dim3(2, 1, BB * HH), blk>>>(
        att, SS, (size_t)HH * NN * SS, (size_t)NN * SS,
        vp,  EE, (size_t)SS * EE,      (size_t)CH,
        cat + (size_t)NN * EE, EE, (size_t)NQ * EE, (size_t)CH,
        nullptr, NN, SS);
    // final projection
    sgemm_f32x2<<<dim3(16, 13, 1), blk>>>(cat, EE, 0, 0, wo, EE, 0, 0, out, EE, 0, 0, bo, BB * NQ, EE);
    (void)in_sizes; (void)n_in; (void)out_size;
}

// round 14
// speedup vs baseline: 1.3709x; 1.3109x over previous
#include <cuda_runtime.h>
#include <cuda_bf16.h>
#include <cstdint>

#define BB 8
#define NQ 200
#define NN 100
#define SS 4096
#define EE 2048
#define HH 8
#define CH 256
#define KC 32
#define NC (EE / KC)          // 64 k-chunks (vp mma path)
#define TILEB 10240           // 128 rows x 80B (32 bf16 + 8B pad)

// ------------- scratch (device bss) -------------
__device__ float g_qp[(size_t)BB * NQ * EE];
__device__ float g_kp[(size_t)BB * SS * EE];
__device__ float g_vp[(size_t)BB * SS * EE];
__device__ float g_kinv[BB * SS];
__device__ float g_q1[(size_t)BB * NN * EE];
__device__ int   g_widx[BB * HH * SS];
__device__ float g_att[(size_t)BB * HH * NN * SS];
__device__ float g_cat[(size_t)BB * NQ * EE];
__device__ int   g_order[BB * HH * SS];
__device__ int   g_offs[BB * HH * (NN + 1)];
// 2-way bf16 splits of v and wv^T
__device__ __nv_bfloat16 g_va1[(size_t)BB * SS * EE];
__device__ __nv_bfloat16 g_va2[(size_t)BB * SS * EE];
__device__ __nv_bfloat16 g_wv1[(size_t)EE * EE];
__device__ __nv_bfloat16 g_wv2[(size_t)EE * EE];

// ------------- helpers -------------
__device__ __forceinline__ unsigned long long pack2(float lo, float hi) {
    unsigned long long r;
    asm("mov.b64 %0, {%1, %2};" : "=l"(r) : "f"(lo), "f"(hi));
    return r;
}
__device__ __forceinline__ void unpack2(unsigned long long p, float& lo, float& hi) {
    asm("mov.b64 {%0, %1}, %2;" : "=f"(lo), "=f"(hi) : "l"(p));
}
__device__ __forceinline__ unsigned long long ffma2(unsigned long long a,
                                                    unsigned long long b,
                                                    unsigned long long c) {
    unsigned long long d;
    asm("fma.rn.f32x2 %0, %1, %2, %3;" : "=l"(d) : "l"(a), "l"(b), "l"(c));
    return d;
}
__device__ __forceinline__ uint32_t s2u(const void* p) {
    uint32_t a;
    asm("{ .reg .u64 t; cvta.to.shared.u64 t, %1; cvt.u32.u64 %0, t; }" : "=r"(a) : "l"(p));
    return a;
}
__device__ __forceinline__ void cp16(uint32_t dst, const void* src) {
    asm volatile("cp.async.cg.shared.global [%0], [%1], 16;" :: "r"(dst), "l"(src));
}
__device__ __forceinline__ uint32_t lds32(uint32_t addr) {
    uint32_t v;
    asm volatile("ld.shared.b32 %0, [%1];" : "=r"(v) : "r"(addr));
    return v;
}
__device__ __forceinline__ void mma_bf16(float* d, uint32_t a0, uint32_t a1,
                                         uint32_t a2, uint32_t a3,
                                         uint32_t b0, uint32_t b1) {
    asm volatile(
        "mma.sync.aligned.m16n8k16.row.col.f32.bf16.bf16.f32 "
        "{%0,%1,%2,%3}, {%4,%5,%6,%7}, {%8,%9}, {%0,%1,%2,%3};"
        : "+f"(d[0]), "+f"(d[1]), "+f"(d[2]), "+f"(d[3])
        : "r"(a0), "r"(a1), "r"(a2), "r"(a3), "r"(b0), "r"(b1));
}

// ------------- JAX threefry2x32 Gumbel (key=[0,42], partitionable) -------------
__device__ __forceinline__ float gumbel_g(unsigned int ctr) {
    unsigned int x0 = 0u, x1 = ctr;
    const unsigned int k0 = 0u, k1 = 42u, k2 = 0x1BD11BDAu ^ 42u;
    x0 += k0; x1 += k1;
#define TFR(r) { x0 += x1; x1 = (x1 << (r)) | (x1 >> (32 - (r))); x1 ^= x0; }
    TFR(13) TFR(15) TFR(26) TFR(6)
    x0 += k1; x1 += k2 + 1u;
    TFR(17) TFR(29) TFR(16) TFR(24)
    x0 += k2; x1 += k0 + 2u;
    TFR(13) TFR(15) TFR(26) TFR(6)
    x0 += k0; x1 += k1 + 3u;
    TFR(17) TFR(29) TFR(16) TFR(24)
    x0 += k1; x1 += k2 + 4u;
    TFR(13) TFR(15) TFR(26) TFR(6)
    x0 += k2; x1 += k0 + 5u;
#undef TFR
    unsigned int bits = x0 ^ x1;
    float f = __uint_as_float((bits >> 9) | 0x3f800000u) - 1.0f;
    const float minv = 1e-6f;
    const float maxv = (float)(1.0 - 1e-6);
    const float span = maxv - minv;
    float u = __fadd_rn(__fmul_rn(f, span), minv);
    u = fmaxf(minv, u);
    return -logf(-logf(u));
}

// ------------- generic f32x2 GEMM (qp / out2 / final; exact fp32) -------------
__global__ __launch_bounds__(256) void sgemm_f32x2(
    const float* __restrict__ A, int lda, size_t aZb, size_t aZh,
    const float* __restrict__ W, int ldw, size_t wZb, size_t wZh,
    float* __restrict__ C, int ldc, size_t cZb, size_t cZh,
    const float* __restrict__ bias, int M, int K)
{
    __shared__ __align__(16) float As[16][128];
    __shared__ __align__(16) float Ws[16][128];
    const int tid  = threadIdx.x;
    const int tm   = (tid >> 4) * 8;
    const int tn   = (tid & 15) * 8;
    const int row0 = blockIdx.y * 128;
    const int col0 = blockIdx.x * 128;
    const int zb = blockIdx.z >> 3, zh = blockIdx.z & 7;
    const float* Az = A + (size_t)zb * aZb + (size_t)zh * aZh;
    const float* Wz = W + (size_t)zb * wZb + (size_t)zh * wZh;
    float* Cz       = C + (size_t)zb * cZb + (size_t)zh * cZh;

    unsigned long long acc[8][4];
#pragma unroll
    for (int i = 0; i < 8; i++)
#pragma unroll
        for (int j = 0; j < 4; j++) acc[i][j] = 0ull;

    const int la_r = tid >> 2, la_c = (tid & 3) * 4;
    const int lw_r = tid >> 5, lw_c = (tid & 31) * 4;

    for (int k0 = 0; k0 < K; k0 += 16) {
#pragma unroll
        for (int i = 0; i < 2; i++) {
            int ar = la_r + i * 64;
            float4 av = make_float4(0.f, 0.f, 0.f, 0.f);
            if (row0 + ar < M)
                av = *(const float4*)(Az + (size_t)(row0 + ar) * lda + k0 + la_c);
            As[la_c + 0][ar] = av.x; As[la_c + 1][ar] = av.y;
            As[la_c + 2][ar] = av.z; As[la_c + 3][ar] = av.w;
        }
#pragma unroll
        for (int i = 0; i < 2; i++) {
            int wr = lw_r + i * 8;
            *(float4*)&Ws[wr][lw_c] =
                *(const float4*)(Wz + (size_t)(k0 + wr) * ldw + col0 + lw_c);
        }
        __syncthreads();
#pragma unroll
        for (int kk = 0; kk < 16; kk++) {
            float a[8], b[8];
            *(float4*)&a[0] = *(const float4*)&As[kk][tm];
            *(float4*)&a[4] = *(const float4*)&As[kk][tm + 4];
            *(float4*)&b[0] = *(const float4*)&Ws[kk][tn];
            *(float4*)&b[4] = *(const float4*)&Ws[kk][tn + 4];
            unsigned long long bp[4];
#pragma unroll
            for (int j = 0; j < 4; j++) bp[j] = pack2(b[2 * j], b[2 * j + 1]);
#pragma unroll
            for (int i = 0; i < 8; i++) {
                unsigned long long ap = pack2(a[i], a[i]);
#pragma unroll
                for (int j = 0; j < 4; j++) acc[i][j] = ffma2(ap, bp[j], acc[i][j]);
            }
        }
        __syncthreads();
    }

#pragma unroll
    for (int i = 0; i < 8; i++) {
        int r = row0 + tm + i;
        if (r < M) {
            float o[8];
#pragma unroll
            for (int j = 0; j < 4; j++) unpack2(acc[i][j], o[2 * j], o[2 * j + 1]);
            if (bias) {
#pragma unroll
                for (int j = 0; j < 8; j++) o[j] += bias[col0 + tn + j];
            }
            *(float4*)(Cz + (size_t)r * ldc + col0 + tn)     = make_float4(o[0], o[1], o[2], o[3]);
            *(float4*)(Cz + (size_t)r * ldc + col0 + tn + 4) = make_float4(o[4], o[5], o[6], o[7]);
        }
    }
}

// ------------- 2-way bf16 split -------------
__global__ __launch_bounds__(256) void split2_kernel(
    const float* __restrict__ x, __nv_bfloat16* __restrict__ h1,
    __nv_bfloat16* __restrict__ h2, size_t n)
{
    size_t i = (size_t)blockIdx.x * blockDim.x + threadIdx.x;
    size_t stride = (size_t)gridDim.x * blockDim.x;
    for (; i < n; i += stride) {
        float v = x[i];
        __nv_bfloat16 a = __float2bfloat16(v);
        float r1 = v - __bfloat162float(a);
        h1[i] = a; h2[i] = __float2bfloat16(r1);
    }
}

// ------------- transpose (EExEE) + 2-way bf16 split -------------
__global__ __launch_bounds__(256) void tsplit2_kernel(
    const float* __restrict__ w, __nv_bfloat16* __restrict__ t1,
    __nv_bfloat16* __restrict__ t2)
{
    __shared__ float tile[32][33];
    int n0 = blockIdx.x * 32, k0 = blockIdx.y * 32;
    int tx = threadIdx.x & 31, ty = threadIdx.x >> 5;
#pragma unroll
    for (int i = 0; i < 4; i++)
        tile[ty + i * 8][tx] = w[(size_t)(k0 + ty + i * 8) * EE + n0 + tx];
    __syncthreads();
#pragma unroll
    for (int i = 0; i < 4; i++) {
        float v = tile[tx][ty + i * 8];
        __nv_bfloat16 a = __float2bfloat16(v);
        float r1 = v - __bfloat162float(a);
        size_t o = (size_t)(n0 + ty + i * 8) * EE + k0 + tx;
        t1[o] = a; t2[o] = __float2bfloat16(r1);
    }
}

// ------------- kp block: fp32 FFMA2, cp.async double-buffered -------------
// C[M,2048] = A[M,2048] @ W[2048,2048] + bias ; M % 128 == 0.
__device__ __forceinline__ void kp_block(
    char* smem, const float* __restrict__ A, const float* __restrict__ W,
    float* __restrict__ C, const float* __restrict__ bias, int bx, int by)
{
    // As: [2][128][20] floats (80B rows, 16B aligned); Ws: [2][16][128]
    float (*As)[128][20] = reinterpret_cast<float (*)[128][20]>(smem);
    float (*Ws)[16][128] = reinterpret_cast<float (*)[16][128]>(smem + 20480);
    const int tid = threadIdx.x;
    const int tm = (tid >> 4) * 8, tn = (tid & 15) * 8;
    const int row0 = by * 128, col0 = bx * 128;

    unsigned long long acc[8][4];
#pragma unroll
    for (int i = 0; i < 8; i++)
#pragma unroll
        for (int j = 0; j < 4; j++) acc[i][j] = 0ull;

    const int a_r = (tid * 2) >> 2,  a_c0 = ((tid * 2) & 3) * 4;
    const int w_r = (tid * 2) >> 5,  w_c0 = ((tid * 2) & 31) * 4;

    auto load = [&](int buf, int c) {
        int k0 = c * 16;
#pragma unroll
        for (int t = 0; t < 2; t++) {
            int idx = tid * 2 + t;
            int ar = idx >> 2, ac = (idx & 3) * 4;
            cp16(s2u(&As[buf][ar][ac]), A + (size_t)(row0 + ar) * EE + k0 + ac);
        }
#pragma unroll
        for (int t = 0; t < 2; t++) {
            int idx = tid * 2 + t;
            int wr = idx >> 5, wc = (idx & 31) * 4;
            cp16(s2u(&Ws[buf][wr][wc]), W + (size_t)(k0 + wr) * EE + col0 + wc);
        }
        asm volatile("cp.async.commit_group;" ::: "memory");
    };
    (void)a_r; (void)a_c0; (void)w_r; (void)w_c0;

    load(0, 0);
    for (int c = 0; c < 128; c++) {
        if (c + 1 < 128) {
            load((c + 1) & 1, c + 1);
            asm volatile("cp.async.wait_group 1;" ::: "memory");
        } else {
            asm volatile("cp.async.wait_group 0;" ::: "memory");
        }
        __syncthreads();
        int buf = c & 1;
#pragma unroll
        for (int kk = 0; kk < 16; kk++) {
            float b[8];
            *(float4*)&b[0] = *(const float4*)&Ws[buf][kk][tn];
            *(float4*)&b[4] = *(const float4*)&Ws[buf][kk][tn + 4];
            unsigned long long bp[4];
#pragma unroll
            for (int j = 0; j < 4; j++) bp[j] = pack2(b[2 * j], b[2 * j + 1]);
#pragma unroll
            for (int i = 0; i < 8; i++) {
                float av = As[buf][tm + i][kk];
                unsigned long long ap = pack2(av, av);
#pragma unroll
                for (int j = 0; j < 4; j++) acc[i][j] = ffma2(ap, bp[j], acc[i][j]);
            }
        }
        __syncthreads();
    }

#pragma unroll
    for (int i = 0; i < 8; i++) {
        int r = row0 + tm + i;
        float o[8];
#pragma unroll
        for (int j = 0; j < 4; j++) unpack2(acc[i][j], o[2 * j], o[2 * j + 1]);
#pragma unroll
        for (int j = 0; j < 8; j++) o[j] += bias[col0 + tn + j];
        *(float4*)(C + (size_t)r * EE + col0 + tn)     = make_float4(o[0], o[1], o[2], o[3]);
        *(float4*)(C + (size_t)r * EE + col0 + tn + 4) = make_float4(o[4], o[5], o[6], o[7]);
    }
}

// ------------- vp block: bf16 x3 (11,12,21) via mma.sync -------------
__device__ __forceinline__ void vp_block(
    char* smem,
    const __nv_bfloat16* __restrict__ A1, const __nv_bfloat16* __restrict__ A2,
    const __nv_bfloat16* __restrict__ B1, const __nv_bfloat16* __restrict__ B2,
    float* __restrict__ C, const float* __restrict__ bias, int bx, int by)
{
    const int tid = threadIdx.x;
    const int wid = tid >> 5, lane = tid & 31;
    const int g = lane >> 2, tig = lane & 3;
    const int wm = (wid >> 2) * 64;
    const int wn = (wid & 3) * 32;
    const int n0 = bx * 128;
    const int m0 = by * 128;
    const uint32_t sbase = s2u(smem);
    const int stageBytes = 4 * TILEB;   // A1,A2,B1,B2 tiles

    float d[4][4][4];
#pragma unroll
    for (int mt = 0; mt < 4; mt++)
#pragma unroll
        for (int nt = 0; nt < 4; nt++)
#pragma unroll
            for (int r = 0; r < 4; r++) d[mt][nt][r] = 0.f;

    const __nv_bfloat16* AP[2] = {A1, A2};
    const __nv_bfloat16* BP[2] = {B1, B2};

    auto load_stage = [&](int buf, int c) {
        uint32_t sb = sbase + (uint32_t)buf * stageBytes;
        const int idx0 = tid * 2;
#pragma unroll
        for (int sp = 0; sp < 2; sp++) {
            const char* ga = (const char*)AP[sp] + ((size_t)m0 * EE + (size_t)c * KC) * 2;
            const char* gb = (const char*)BP[sp] + ((size_t)n0 * EE + (size_t)c * KC) * 2;
            uint32_t ta = sb + sp * TILEB;
            uint32_t tb = sb + (2 + sp) * TILEB;
#pragma unroll
            for (int t = 0; t < 2; t++) {
                int idx = idx0 + t;
                int row = idx >> 2, ch = idx & 3;
                cp16(ta + row * 80 + ch * 16, ga + (size_t)row * (EE * 2) + ch * 16);
                cp16(tb + row * 80 + ch * 16, gb + (size_t)row * (EE * 2) + ch * 16);
            }
        }
        asm volatile("cp.async.commit_group;" ::: "memory");
    };

    const int pa[3] = {0, 0, 1};
    const int pb[3] = {0, 1, 0};

    load_stage(0, 0);
    for (int c = 0; c < NC; c++) {
        if (c + 1 < NC) {
            load_stage((c + 1) & 1, c + 1);
            asm volatile("cp.async.wait_group 1;" ::: "memory");
        } else {
            asm volatile("cp.async.wait_group 0;" ::: "memory");
        }
        __syncthreads();

        uint32_t sb = sbase + (uint32_t)(c & 1) * stageBytes;
#pragma unroll
        for (int p = 0; p < 3; p++) {
            uint32_t aBase = sb + pa[p] * TILEB;
            uint32_t bBase = sb + (2 + pb[p]) * TILEB;
#pragma unroll
            for (int ks = 0; ks < 2; ks++) {
                const int kk = ks * 16;
                uint32_t bf[4][2];
#pragma unroll
                for (int nt = 0; nt < 4; nt++) {
                    uint32_t ba = bBase + (wn + nt * 8 + g) * 80 + (kk + tig * 2) * 2;
                    bf[nt][0] = lds32(ba);
                    bf[nt][1] = lds32(ba + 16);
                }
#pragma unroll
                for (int mt = 0; mt < 4; mt++) {
                    uint32_t aa = aBase + (wm + mt * 16 + g) * 80 + (kk + tig * 2) * 2;
                    uint32_t a0 = lds32(aa);
                    uint32_t a1 = lds32(aa + 8 * 80);
                    uint32_t a2 = lds32(aa + 16);
                    uint32_t a3 = lds32(aa + 8 * 80 + 16);
#pragma unroll
                    for (int nt = 0; nt < 4; nt++)
                        mma_bf16(d[mt][nt], a0, a1, a2, a3, bf[nt][0], bf[nt][1]);
                }
            }
        }
        __syncthreads();
    }

#pragma unroll
    for (int mt = 0; mt < 4; mt++) {
        int r0 = m0 + wm + mt * 16 + g;
#pragma unroll
        for (int nt = 0; nt < 4; nt++) {
            int col = n0 + wn + nt * 8 + tig * 2;
            float b0 = bias[col], b1 = bias[col + 1];
            float2 v0 = make_float2(d[mt][nt][0] + b0, d[mt][nt][1] + b1);
            float2 v1 = make_float2(d[mt][nt][2] + b0, d[mt][nt][3] + b1);
            *(float2*)(C + (size_t)r0 * EE + col)       = v0;
            *(float2*)(C + (size_t)(r0 + 8) * EE + col) = v1;
        }
    }
}

// ------------- fused projection: kp (fp32/FMA pipe) + vp (bf16/tensor pipe) -------------
// grid (32, 256): x<16 -> kp column x ; x>=16 -> vp column x-16. Interleaved bids
// co-schedule both kinds per SM so FMA and tensor pipes overlap.
__global__ __launch_bounds__(256, 2) void proj_fused(
    const float* __restrict__ kA, const float* __restrict__ kW, float* __restrict__ kp,
    const float* __restrict__ bk,
    const __nv_bfloat16* __restrict__ va1, const __nv_bfloat16* __restrict__ va2,
    const __nv_bfloat16* __restrict__ wv1, const __nv_bfloat16* __restrict__ wv2,
    float* __restrict__ vp, const float* __restrict__ bv)
{
    extern __shared__ __align__(16) char smem[];
    if (blockIdx.x < 16)
        kp_block(smem, kA, kW, kp, bk, blockIdx.x, blockIdx.y);
    else
        vp_block(smem, va1, va2, wv1, wv2, vp, bv, blockIdx.x - 16, blockIdx.y);
}

// ------------- kp row inverse norms -------------
__global__ __launch_bounds__(256) void knorm_kernel(const float* __restrict__ kp,
                                                    float* __restrict__ kinv)
{
    __shared__ float red[8];
    const float* p = kp + (size_t)blockIdx.x * EE;
    float ss = 0.f;
#pragma unroll
    for (int it = 0; it < 2; it++) {
        float4 v = *(const float4*)(p + threadIdx.x * 4 + it * 1024);
        ss += v.x * v.x + v.y * v.y + v.z * v.z + v.w * v.w;
    }
#pragma unroll
    for (int o = 16; o; o >>= 1) ss += __shfl_xor_sync(0xffffffffu, ss, o);
    if ((threadIdx.x & 31) == 0) red[threadIdx.x >> 5] = ss;
    __syncthreads();
    if (threadIdx.x == 0) {
        float t = 0.f;
#pragma unroll
        for (int w = 0; w < 8; w++) t += red[w];
        kinv[blockIdx.x] = 1.0f / sqrtf(t);
    }
}

// ------------- q1 = normalize(qp rows [:,0:100,:]) -------------
__global__ __launch_bounds__(256) void q1norm_kernel(const float* __restrict__ qp,
                                                     float* __restrict__ q1)
{
    __shared__ float red[8];
    __shared__ float s_inv;
    int row = blockIdx.x;
    int b = row / NN, qq = row % NN;
    const float* p = qp + (size_t)(b * NQ + qq) * EE;
    float ss = 0.f;
#pragma unroll
    for (int it = 0; it < 2; it++) {
        float4 v = *(const float4*)(p + threadIdx.x * 4 + it * 1024);
        ss += v.x * v.x + v.y * v.y + v.z * v.z + v.w * v.w;
    }
#pragma unroll
    for (int o = 16; o; o >>= 1) ss += __shfl_xor_sync(0xffffffffu, ss, o);
    if ((threadIdx.x & 31) == 0) red[threadIdx.x >> 5] = ss;
    __syncthreads();
    if (threadIdx.x == 0) {
        float t = 0.f;
#pragma unroll
        for (int w = 0; w < 8; w++) t += red[w];
        s_inv = 1.0f / sqrtf(t);
    }
    __syncthreads();
    float inv = s_inv;
    float* dst = q1 + (size_t)row * EE;
#pragma unroll
    for (int it = 0; it < 2; it++) {
        int i = threadIdx.x * 4 + it * 1024;
        float4 v = *(const float4*)(p + i);
        v.x *= inv; v.y *= inv; v.z *= inv; v.w *= inv;
        *(float4*)(dst + i) = v;
    }
}

// ------------- fused attn1-argmax + attn2-logits (exact fp32, ffma2 inner) -------------
__global__ __launch_bounds__(256) void attn_fused_kernel(
    const float* __restrict__ kp, const float* __restrict__ kinv,
    const float* __restrict__ q1, const float* __restrict__ qp,
    float* __restrict__ att, int* __restrict__ widx)
{
    __shared__ __align__(16) float As1[16][128];
    __shared__ __align__(16) float As2[16][128];
    __shared__ __align__(16) float Bs[16][64];
    __shared__ float rbest[64][16];
    __shared__ int   rq[64][16];

    const int tid = threadIdx.x;
    const int bh = blockIdx.z;
    const int b = bh >> 3, h = bh & 7;
    const int s0 = blockIdx.x * 64;
    const int tm = (tid >> 4) * 8;
    const int tn = (tid & 15) * 4;

    unsigned long long a1p[8][2], a2p[8][2];
#pragma unroll
    for (int i = 0; i < 8; i++) {
        a1p[i][0] = a1p[i][1] = 0ull;
        a2p[i][0] = a2p[i][1] = 0ull;
    }

    for (int c0 = 0; c0 < CH; c0 += 16) {
#pragma unroll
        for (int i = 0; i < 2; i++) {
            int ar = (tid >> 2) + i * 64;
            int ac = (tid & 3) * 4;
            float4 v1 = make_float4(0.f, 0.f, 0.f, 0.f), v2 = v1;
            if (ar < NN) {
                v1 = *(const float4*)(q1 + (size_t)(b * NN + ar) * EE + h * CH + c0 + ac);
                v2 = *(const float4*)(qp + (size_t)(b * NQ + NN + ar) * EE + h * CH + c0 + ac);
            }
            As1[ac + 0][ar] = v1.x; As1[ac + 1][ar] = v1.y; As1[ac + 2][ar] = v1.z; As1[ac + 3][ar] = v1.w;
            As2[ac + 0][ar] = v2.x; As2[ac + 1][ar] = v2.y; As2[ac + 2][ar] = v2.z; As2[ac + 3][ar] = v2.w;
        }
        {
            int sl = tid >> 2, cl = (tid & 3) * 4;
            float4 kv = *(const float4*)(kp + (size_t)(b * SS + s0 + sl) * EE + h * CH + c0 + cl);
            Bs[cl + 0][sl] = kv.x; Bs[cl + 1][sl] = kv.y; Bs[cl + 2][sl] = kv.z; Bs[cl + 3][sl] = kv.w;
        }
        __syncthreads();
#pragma unroll
        for (int kk = 0; kk < 16; kk++) {
            float a1[8], a2[8], bb[4];
            *(float4*)&a1[0] = *(const float4*)&As1[kk][tm];
            *(float4*)&a1[4] = *(const float4*)&As1[kk][tm + 4];
            *(float4*)&a2[0] = *(const float4*)&As2[kk][tm];
            *(float4*)&a2[4] = *(const float4*)&As2[kk][tm + 4];
            *(float4*)&bb[0] = *(const float4*)&Bs[kk][tn];
            unsigned long long bp0 = pack2(bb[0], bb[1]);
            unsigned long long bp1 = pack2(bb[2], bb[3]);
#pragma unroll
            for (int i = 0; i < 8; i++) {
                unsigned long long ap1 = pack2(a1[i], a1[i]);
                unsigned long long ap2 = pack2(a2[i], a2[i]);
                a1p[i][0] = ffma2(ap1, bp0, a1p[i][0]);
                a1p[i][1] = ffma2(ap1, bp1, a1p[i][1]);
                a2p[i][0] = ffma2(ap2, bp0, a2p[i][0]);
                a2p[i][1] = ffma2(ap2, bp1, a2p[i][1]);
            }
        }
        __syncthreads();
    }

    float kiv[4];
#pragma unroll
    for (int j = 0; j < 4; j++) kiv[j] = kinv[b * SS + s0 + tn + j];

    float best[4]; int bq[4];
#pragma unroll
    for (int j = 0; j < 4; j++) { best[j] = -3.0e38f; bq[j] = 0; }

#pragma unroll
    for (int i = 0; i < 8; i++) {
        int qv = tm + i;
        if (qv < NN) {
            float acc1[4], acc2[4];
            unpack2(a1p[i][0], acc1[0], acc1[1]);
            unpack2(a1p[i][1], acc1[2], acc1[3]);
            unpack2(a2p[i][0], acc2[0], acc2[1]);
            unpack2(a2p[i][1], acc2[2], acc2[3]);
            float4 st;
            st.x = acc2[0] * 0.0625f; st.y = acc2[1] * 0.0625f;
            st.z = acc2[2] * 0.0625f; st.w = acc2[3] * 0.0625f;
            *(float4*)(att + (size_t)(bh * NN + qv) * SS + s0 + tn) = st;
#pragma unroll
            for (int j = 0; j < 4; j++) {
                unsigned int ctr = ((unsigned int)(bh * NN + qv) << 12)
                                 | (unsigned int)(s0 + tn + j);
                float val = acc1[j] * kiv[j] + gumbel_g(ctr);
                if (val > best[j]) { best[j] = val; bq[j] = qv; }
            }
        }
    }
#pragma unroll
    for (int j = 0; j < 4; j++) {
        rbest[tn + j][tid >> 4] = best[j];
        rq[tn + j][tid >> 4]    = bq[j];
    }
    __syncthreads();
    if (tid < 64) {
        float bv = rbest[tid][0]; int bqq = rq[tid][0];
#pragma unroll
        for (int r = 1; r < 16; r++) {
            float vv = rbest[tid][r]; int qq = rq[tid][r];
            if (vv > bv || (vv == bv && qq < bqq)) { bv = vv; bqq = qq; }
        }
        widx[bh * SS + s0 + tid] = bqq;
    }
}

// ------------- softmax over 4096-wide rows of g_att (in place) -------------
__global__ __launch_bounds__(256) void softmax_kernel(float* __restrict__ att)
{
    __shared__ float red[8];
    __shared__ float s_b;
    float* p = att + (size_t)blockIdx.x * SS;
    float v[16];
#pragma unroll
    for (int c = 0; c < 4; c++) {
        float4 t = *(const float4*)(p + threadIdx.x * 4 + c * 1024);
        v[c * 4 + 0] = t.x; v[c * 4 + 1] = t.y; v[c * 4 + 2] = t.z; v[c * 4 + 3] = t.w;
    }
    float m = -3.0e38f;
#pragma unroll
    for (int i = 0; i < 16; i++) m = fmaxf(m, v[i]);
#pragma unroll
    for (int o = 16; o; o >>= 1) m = fmaxf(m, __shfl_xor_sync(0xffffffffu, m, o));
    if ((threadIdx.x & 31) == 0) red[threadIdx.x >> 5] = m;
    __syncthreads();
    if (threadIdx.x == 0) {
        float t = red[0];
#pragma unroll
        for (int w = 1; w < 8; w++) t = fmaxf(t, red[w]);
        s_b = t;
    }
    __syncthreads();
    float mx = s_b;
    float s = 0.f;
#pragma unroll
    for (int i = 0; i < 16; i++) { v[i] = expf(v[i] - mx); s += v[i]; }
#pragma unroll
    for (int o = 16; o; o >>= 1) s += __shfl_xor_sync(0xffffffffu, s, o);
    __syncthreads();
    if ((threadIdx.x & 31) == 0) red[threadIdx.x >> 5] = s;
    __syncthreads();
    if (threadIdx.x == 0) {
        float t = 0.f;
#pragma unroll
        for (int w = 0; w < 8; w++) t += red[w];
        s_b = t;
    }
    __syncthreads();
    float sum = s_b;
#pragma unroll
    for (int c = 0; c < 4; c++) {
        float4 t;
        t.x = v[c * 4 + 0] / sum; t.y = v[c * 4 + 1] / sum;
        t.z = v[c * 4 + 2] / sum; t.w = v[c * 4 + 3] / sum;
        *(float4*)(p + threadIdx.x * 4 + c * 1024) = t;
    }
}

// ------------- bucket winners: stable counting sort of s by widx -------------
__global__ __launch_bounds__(128) void bucket_kernel(
    const int* __restrict__ widx, int* __restrict__ order, int* __restrict__ offs)
{
    __shared__ int sw[SS];
    __shared__ int cnt[NN];
    __shared__ int off[NN + 1];
    int bh = blockIdx.x;
    int tid = threadIdx.x;
    for (int i = tid; i < SS; i += 128) sw[i] = widx[bh * SS + i];
    __syncthreads();
    if (tid < NN) {
        int c = 0;
        for (int s = 0; s < SS; s++) c += (sw[s] == tid);
        cnt[tid] = c;
    }
    __syncthreads();
    if (tid == 0) {
        int a = 0;
        for (int i = 0; i < NN; i++) { off[i] = a; a += cnt[i]; }
        off[NN] = a;
    }
    __syncthreads();
    for (int i = tid; i < NN + 1; i += 128) offs[bh * (NN + 1) + i] = off[i];
    if (tid < NN) {
        int p = off[tid];
        for (int s = 0; s < SS; s++)
            if (sw[s] == tid) order[bh * SS + p++] = s;
    }
}

// ------------- out1: list-driven gather-sum of vp rows -------------
__global__ __launch_bounds__(256) void out1_list_kernel(
    const float* __restrict__ vp, const int* __restrict__ order,
    const int* __restrict__ offs, float* __restrict__ cat)
{
    int qv = blockIdx.x;
    int bh = blockIdx.y;
    int b = bh >> 3, h = bh & 7;
    int o0 = offs[bh * (NN + 1) + qv];
    int o1 = offs[bh * (NN + 1) + qv + 1];
    int c = threadIdx.x;
    const float* vbase = vp + (size_t)b * SS * EE + h * CH + c;
    float acc = 0.f;
    for (int i = o0; i < o1; i++) {
        int s = __ldg(order + bh * SS + i);
        acc += vbase[(size_t)s * EE];
    }
    cat[((size_t)b * NQ + qv) * EE + h * CH + c] = acc;
}

// ------------- launcher -------------
extern "C" void kernel_launch(void* const* d_in, const int* in_sizes, int n_in,
                              void* d_out, int out_size) {
    const float* q  = (const float*)d_in[0];
    const float* k  = (const float*)d_in[1];
    const float* v  = (const float*)d_in[2];
    const float* wq = (const float*)d_in[3];
    const float* bq = (const float*)d_in[4];
    const float* wk = (const float*)d_in[5];
    const float* bk = (const float*)d_in[6];
    const float* wv = (const float*)d_in[7];
    const float* bv = (const float*)d_in[8];
    const float* wo = (const float*)d_in[9];
    const float* bo = (const float*)d_in[10];
    float* out = (float*)d_out;

    float *qp, *kp, *vp, *kinv, *q1, *att, *cat; int *widx, *order, *offs;
    __nv_bfloat16 *va1, *va2, *wv1, *wv2;
    cudaGetSymbolAddress((void**)&qp,    g_qp);
    cudaGetSymbolAddress((void**)&kp,    g_kp);
    cudaGetSymbolAddress((void**)&vp,    g_vp);
    cudaGetSymbolAddress((void**)&kinv,  g_kinv);
    cudaGetSymbolAddress((void**)&q1,    g_q1);
    cudaGetSymbolAddress((void**)&widx,  g_widx);
    cudaGetSymbolAddress((void**)&att,   g_att);
    cudaGetSymbolAddress((void**)&cat,   g_cat);
    cudaGetSymbolAddress((void**)&order, g_order);
    cudaGetSymbolAddress((void**)&offs,  g_offs);
    cudaGetSymbolAddress((void**)&va1,   g_va1);
    cudaGetSymbolAddress((void**)&va2,   g_va2);
    cudaGetSymbolAddress((void**)&wv1,   g_wv1);
    cudaGetSymbolAddress((void**)&wv2,   g_wv2);

    const int proj_smem = 4 * TILEB * 2;   // 81920 (vp stage x2; kp uses 36864 of it)
    cudaFuncSetAttribute(proj_fused, cudaFuncAttributeMaxDynamicSharedMemorySize, proj_smem);

    dim3 blk(256);
    const size_t nkv = (size_t)BB * SS * EE;
    // v / wv^T 2-way bf16 splits
    split2_kernel<<<8192, blk>>>(v, va1, va2, nkv);
    tsplit2_kernel<<<dim3(64, 64), blk>>>(wv, wv1, wv2);
    // qp: exact fp32
    sgemm_f32x2<<<dim3(16, 13, 1), blk>>>(q, EE, 0, 0, wq, EE, 0, 0, qp, EE, 0, 0, bq, BB * NQ, EE);
    // kp (fp32, FMA pipe) + vp (bf16x3, tensor pipe) fused & overlapped
    proj_fused<<<dim3(32, 256), blk, proj_smem>>>(k, wk, kp, bk, va1, va2, wv1, wv2, vp, bv);
    // norms
    knorm_kernel<<<BB * SS, blk>>>(kp, kinv);
    q1norm_kernel<<<BB * NN, blk>>>(qp, q1);
    // fused attn logits + gumbel argmax
    attn_fused_kernel<<<dim3(SS / 64, 1, BB * HH), blk>>>(kp, kinv, q1, qp, att, widx);
    // attn2 softmax
    softmax_kernel<<<BB * HH * NN, blk>>>(att);
    // out1: stable bucket + list gather
    bucket_kernel<<<BB * HH, 128>>>(widx, order, offs);
    out1_list_kernel<<<dim3(NN, BB * HH), blk>>>(vp, order, offs, cat);
    // out2 = P @ Vh
    sgemm_f32x2<<<dim3(2, 1, BB * HH), blk>>>(
        att, SS, (size_t)HH * NN * SS, (size_t)NN * SS,
        vp,  EE, (size_t)SS * EE,      (size_t)CH,
        cat + (size_t)NN * EE, EE, (size_t)NQ * EE, (size_t)CH,
        nullptr, NN, SS);
    // final projection
    sgemm_f32x2<<<dim3(16, 13, 1), blk>>>(cat, EE, 0, 0, wo, EE, 0, 0, out, EE, 0, 0, bo, BB * NQ, EE);
    (void)in_sizes; (void)n_in; (void)out_size;
}